// round 11
// baseline (speedup 1.0000x reference)
#include <cuda_runtime.h>
#include <cuda_bf16.h>

// FQCNN_layer: closed-form evaluation.
//
// Math: expval(Z on wire 4) is invariant under the post-encoding circuit
// (H on wire 5, controlled-U3s on wire 6: unitaries on wires != 4 preserve
// the wire-4 marginal). Summing the 16 equal-weight H^{x4} branches of the
// commuting (controlled-)RYs on wire 4:
//   <Z> = (1/16)[ 8cos(A) + 2cos(A+u) + 2cos(A+v) + cos(A+w)
//                + cos(A+u+w) + cos(A+v+w) + cos(A+u+v+w) ]
// with (A,u,v,w) = (im[j,k], im[j,k+1], im[j+1,k], im[j+1,k+1]).
// Sum-to-product (exact):
//   2c(A+u)+2c(A+v)                      = 4 c((u-v)/2) c(A+m),  m=(u+v)/2
//   c(A+w)+c(A+u+w)+c(A+v+w)+c(A+u+v+w) = 4 c(u/2) c(v/2) c(A+m+w)
// => out = 0.5 c(A) + 0.25 [ c((u-v)/2) c(A+m) + c(u/2) c(v/2) c(A+m+w) ]
// (6 MUFU.COS). U3_w is provably unused.
//
// R10: launch shape fixed at measured optimum (256 thr x 768 blocks, one
// output/thread, ncu 4.83-4.86us across rounds). This round trims the
// pre-load prologue: exact grid => no bounds check, and the input index
// collapses to base = 2*i - (i & 63):
//   i    = bc*4096 + oh*64 + ow   (output, float units)
//   base = bc*8192 + oh*128 + ow  (input, float2 units)  = i + (i & ~63).

#define N_OUT 196608   // 16*3*64*64 == 768 * 256 exactly

__global__ __launch_bounds__(256) void fqcnn_kernel(const float2* __restrict__ in2,
                                                    float* __restrict__ out) {
    int i = blockIdx.x * blockDim.x + threadIdx.x;   // exact grid, no tail

    int base = 2 * i - (i & 63);        // float2 index of (A,u) pair
    const float2 r0 = in2[base];        // row 2*oh   : A u
    const float2 r1 = in2[base + 64];   // row 2*oh+1 : v w

    float A = r0.x, u = r0.y, v = r1.x, w = r1.y;

    float hu = 0.5f * u;
    float hv = 0.5f * v;
    float m  = hu + hv;
    float d  = hu - hv;

    float cA  = __cosf(A);
    float cd  = __cosf(d);
    float cm  = __cosf(A + m);
    float chu = __cosf(hu);
    float chv = __cosf(hv);
    float cw  = __cosf(A + m + w);

    out[i] = 0.5f * cA + 0.25f * (cd * cm + chu * chv * cw);
}

extern "C" void kernel_launch(void* const* d_in, const int* in_sizes, int n_in,
                              void* d_out, int out_size) {
    const float2* x  = (const float2*)d_in[0];   // [16,3,128,128] fp32
    // d_in[1] = U3_w — unused (see math above)
    float* out = (float*)d_out;                  // [16,3,64,64] fp32

    fqcnn_kernel<<<N_OUT / 256, 256>>>(x, out);
}

// round 12
// speedup vs baseline: 2.8571x; 2.8571x over previous
#include <cuda_runtime.h>
#include <cuda_bf16.h>

// FQCNN_layer: closed-form evaluation.
//
// Math: expval(Z on wire 4) is invariant under the post-encoding circuit
// (H on wire 5, controlled-U3s on wire 6: unitaries on wires != 4 preserve
// the wire-4 marginal). Summing the 16 equal-weight H^{x4} branches of the
// commuting (controlled-)RYs on wire 4:
//   <Z> = (1/16)[ 8cos(A) + 2cos(A+u) + 2cos(A+v) + cos(A+w)
//                + cos(A+u+w) + cos(A+v+w) + cos(A+u+v+w) ]
// with (A,u,v,w) = (im[j,k], im[j,k+1], im[j+1,k], im[j+1,k+1]).
// Sum-to-product (exact):
//   2c(A+u)+2c(A+v)                      = 4 c((u-v)/2) c(A+m),  m=(u+v)/2
//   c(A+w)+c(A+u+w)+c(A+v+w)+c(A+u+v+w) = 4 c(u/2) c(v/2) c(A+m+w)
// => out = 0.5 c(A) + 0.25 [ c((u-v)/2) c(A+m) + c(u/2) c(v/2) c(A+m+w) ]
// (6 MUFU.COS). U3_w is provably unused.
//
// Device time has been pinned at 4.83us across R4/R8/R10 regardless of body
// tweaks (all pipes <9% -> launch/ramp floor). R11 tests the last untried
// shape axis: 512-thread CTAs (384 blocks), same warp count, half the CTA
// scheduling events. Body = best-measured one-output/thread form with
// collapsed indexing base = 2*i - (i & 63).

#define N_OUT 196608   // 16*3*64*64 == 384 * 512 exactly

__global__ __launch_bounds__(512) void fqcnn_kernel(const float2* __restrict__ in2,
                                                    float* __restrict__ out) {
    int i = blockIdx.x * blockDim.x + threadIdx.x;   // exact grid, no tail

    int base = 2 * i - (i & 63);        // float2 index of (A,u) pair
    const float2 r0 = in2[base];        // row 2*oh   : A u
    const float2 r1 = in2[base + 64];   // row 2*oh+1 : v w

    float A = r0.x, u = r0.y, v = r1.x, w = r1.y;

    float hu = 0.5f * u;
    float hv = 0.5f * v;
    float m  = hu + hv;
    float d  = hu - hv;

    float cA  = __cosf(A);
    float cd  = __cosf(d);
    float cm  = __cosf(A + m);
    float chu = __cosf(hu);
    float chv = __cosf(hv);
    float cw  = __cosf(A + m + w);

    out[i] = 0.5f * cA + 0.25f * (cd * cm + chu * chv * cw);
}

extern "C" void kernel_launch(void* const* d_in, const int* in_sizes, int n_in,
                              void* d_out, int out_size) {
    const float2* x  = (const float2*)d_in[0];   // [16,3,128,128] fp32
    // d_in[1] = U3_w — unused (see math above)
    float* out = (float*)d_out;                  // [16,3,64,64] fp32

    fqcnn_kernel<<<N_OUT / 512, 512>>>(x, out);
}